// round 13
// baseline (speedup 1.0000x reference)
#include <cuda_runtime.h>
#include <cstdint>

#define NB   2
#define NC   64
#define NH   32
#define NX   64
#define NY   64
#define NZ   64
#define TABD 6
#define F32_EPS 1.1920928955078125e-07f

// Overflow-safe fast tanh: tanh(x) = sign(x) * (1 - t)/(1 + t), t = exp(-2|x|)
__device__ __forceinline__ float fast_tanh(float x) {
    float ax = fabsf(x);
    float t  = __expf(-2.0f * ax);
    float r  = __fdividef(1.0f - t, 1.0f + t);
    return copysignf(r, x);
}

__device__ __forceinline__ float fast_sigmoid(float x) {
    return __fdividef(1.0f, 1.0f + __expf(-x));
}

// Fused kernel: 256 threads, one block per (b,c, group-of-8 x-slices) = 128 KB.
// occ 4 -> 64-reg budget: inner loop holds EIGHT independent float4 loads in
// flight, then eight stores — long unidirectional DRAM bursts to amortize
// read/write bus turnaround (the ~65% ceiling seen at batch<=4).
__global__ void __launch_bounds__(256, 4)
fused_kernel(const float* __restrict__ x,
             const float* __restrict__ tab,
             const float* __restrict__ w1, const float* __restrict__ b1,
             const float* __restrict__ w2, const float* __restrict__ b2,
             const float* __restrict__ wp, const float* __restrict__ bp,
             const float* __restrict__ ws, const float* __restrict__ bs,
             float* __restrict__ out, float* __restrict__ l2_out)
{
    __shared__ __align__(16) float s_w1[192];        // w1 [32][6] flat
    __shared__ float s_w2[32 * 33];                  // w2 padded: row j at j*33
    __shared__ __align__(16) float s_gy[NY];
    __shared__ __align__(16) float s_gz[NZ];
    __shared__ float s_ax[8];                        // (1-scale)*gx for 8 slices
    __shared__ float s_emb [NB][NH];
    __shared__ float s_emb2[NB][NH];
    __shared__ float s_param[8];       // 0:scale 1:shift 2-4:mu_abc 5-7:sigma_abc
    __shared__ float s_sq[640];        // block 0 only

    const int t    = threadIdx.x;      // 0..255
    const int lane = t & 31;
    const int warp = t >> 5;           // 0..7
    const int blk  = blockIdx.x;       // 0..1023
    const int bc   = blk >> 3;         // 0..127
    const int xg   = blk & 7;          // 0..7 (group of 8 x-slices)
    const int b    = bc >> 6;
    const int c    = bc & 63;

    // ---- Stage weights coalesced: w1 (48 float4), w2 (256 float4) ----
    if (t < 48) ((float4*)s_w1)[t] = ((const float4*)w1)[t];
    {
        float4 v = ((const float4*)w2)[t];
        int e0 = t * 4;
        s_w2[((e0    ) >> 5) * 33 + ((e0    ) & 31)] = v.x;
        s_w2[((e0 + 1) >> 5) * 33 + ((e0 + 1) & 31)] = v.y;
        s_w2[((e0 + 2) >> 5) * 33 + ((e0 + 2) & 31)] = v.z;
        s_w2[((e0 + 3) >> 5) * 33 + ((e0 + 3) & 31)] = v.w;
    }
    __syncthreads();

    // ---- MLP layer 1: emb = tanh(tab @ w1.T + b1)  [2,32], from smem ----
    if (t < NB * NH) {
        int bb = t >> 5, j = t & 31;
        float acc = b1[j];
        #pragma unroll
        for (int k = 0; k < TABD; k++) acc += tab[bb * TABD + k] * s_w1[j * TABD + k];
        s_emb[bb][j] = fast_tanh(acc);
    }
    __syncthreads();

    // ---- MLP layer 2: emb2 = tanh(emb @ w2.T + b2)  [2,32], padded smem ----
    if (t < NB * NH) {
        int bb = t >> 5, j = t & 31;
        float acc = b2[j];
        #pragma unroll
        for (int k = 0; k < NH; k++) acc += s_emb[bb][k] * s_w2[j * 33 + k];
        s_emb2[bb][j] = fast_tanh(acc);
    }
    __syncthreads();

    // ---- 8 head params for THIS (b,c): one warp-dot each ----
    {
        float e = s_emb2[b][lane];
        float wgt, bias;
        if (warp < 5) {                // scale, shift, mu_a, mu_b, mu_c
            int row = warp * 64 + c;
            wgt  = wp[row * NH + lane];
            bias = bp[row];
        } else {                       // sigma_a, sigma_b, sigma_c
            int row = (warp - 5) * 64 + c;
            wgt  = ws[row * NH + lane];
            bias = bs[row];
        }
        float acc = e * wgt;
        #pragma unroll
        for (int off = 16; off > 0; off >>= 1)
            acc += __shfl_down_sync(0xffffffffu, acc, off);
        if (lane == 0) {
            acc += bias;
            if (warp >= 2 && warp <= 4) acc = fast_tanh(acc);
            else if (warp >= 5)         acc = fast_sigmoid(acc);
            s_param[warp] = acc;
        }
    }
    __syncthreads();

    // ---- Gaussian tables for this block ----
    if (t < 64) {                      // gy
        float mup = s_param[3] * 32.0f + 31.5f;
        float sgp = s_param[6] * 3.5f + F32_EPS;
        float d = __fdividef((float)t - mup, sgp);
        s_gy[t] = __expf(-0.5f * d * d);
    } else if (t < 128) {              // gz
        int i = t - 64;
        float mup = s_param[4] * 32.0f + 31.5f;
        float sgp = s_param[7] * 3.5f + F32_EPS;
        float d = __fdividef((float)i - mup, sgp);
        s_gz[i] = __expf(-0.5f * d * d);
    } else if (t < 136) {              // ax for the 8 x-slices of this block
        int xi = xg * 8 + (t - 128);
        float mup = s_param[2] * 32.0f + 31.5f;
        float sgp = s_param[5] * 3.5f + F32_EPS;
        float d = __fdividef((float)xi - mup, sgp);
        s_ax[t - 128] = (1.0f - s_param[0]) * __expf(-0.5f * d * d);
    }

    // ---- Block 0 only: scalar l2 over all 128 (b,c) x 5 param groups ----
    if (blockIdx.x == 0) {
        for (int o = t; o < 640; o += 256) {
            int g = o >> 7;            // 0:scale 1:shift 2-4:sigma
            int r = o & 127;
            int bb = r >> 6, cc = r & 63;
            float acc, v;
            if (g < 2) {
                int row = g * 64 + cc;
                acc = bp[row];
                #pragma unroll
                for (int k = 0; k < NH; k++) acc += s_emb2[bb][k] * wp[row * NH + k];
                v = acc;
            } else {
                int row = (g - 2) * 64 + cc;
                acc = bs[row];
                #pragma unroll
                for (int k = 0; k < NH; k++) acc += s_emb2[bb][k] * ws[row * NH + k];
                v = fast_sigmoid(acc);
            }
            s_sq[o] = v * v;
        }
        __syncthreads();
        if (t < 32) {
            float total = 0.0f;
            #pragma unroll
            for (int g = 0; g < 5; g++) {
                float s = s_sq[g * 128 + t] + s_sq[g * 128 + t + 32]
                        + s_sq[g * 128 + t + 64] + s_sq[g * 128 + t + 96];
                #pragma unroll
                for (int off = 16; off > 0; off >>= 1)
                    s += __shfl_down_sync(0xffffffffu, s, off);
                total += sqrtf(s);
            }
            if (t == 0 && l2_out != nullptr) *l2_out = total;
        }
    }
    __syncthreads();   // publishes s_gy / s_gz / s_ax / s_param

    const float sh = s_param[1];

    // ---- Streaming loop: 8 independent loads, then 8 stores per iteration.
    //      Same yz-offset across the batch -> one gy/gz lookup serves all 8. ----
    const size_t base = (size_t)blk * 32768;   // 8 slices * 4096 floats
    const float4* __restrict__ xp = (const float4*)(x   + base);
    float4*       __restrict__ op = (float4*)      (out + base);

    #pragma unroll
    for (int it = 0; it < 4; it++) {
        int idx4 = t + it * 256;               // 0..1023 within a slice
        int y    = idx4 >> 4;
        int z4   = (idx4 & 15) << 2;

        // 8 independent loads (slices 0..7) — long read burst
        float4 v[8];
        #pragma unroll
        for (int p = 0; p < 8; p++)
            v[p] = __ldcs(&xp[idx4 + p * 1024]);

        float gyv = s_gy[y];
        float4 gz = *(const float4*)&s_gz[z4];
        float gxx = gyv * gz.x, gyy = gyv * gz.y, gzz = gyv * gz.z, gww = gyv * gz.w;

        // 8 stores — long write burst
        #pragma unroll
        for (int p = 0; p < 8; p++) {
            float a = s_ax[p];
            float4 o;
            o.x = fmaf(v[p].x, a * gxx, sh);
            o.y = fmaf(v[p].y, a * gyy, sh);
            o.z = fmaf(v[p].z, a * gzz, sh);
            o.w = fmaf(v[p].w, a * gww, sh);
            __stcs(&op[idx4 + p * 1024], o);
        }
    }
}

extern "C" void kernel_launch(void* const* d_in, const int* in_sizes, int n_in,
                              void* d_out, int out_size)
{
    const float* x   = (const float*)d_in[0];
    const float* tab = (const float*)d_in[1];
    const float* w1  = (const float*)d_in[2];
    const float* b1  = (const float*)d_in[3];
    const float* w2  = (const float*)d_in[4];
    const float* b2  = (const float*)d_in[5];
    const float* wp  = (const float*)d_in[6];
    const float* bp  = (const float*)d_in[7];
    const float* ws  = (const float*)d_in[8];
    const float* bs  = (const float*)d_in[9];

    float* out = (float*)d_out;
    const long long n_vol = (long long)NB * NC * NX * NY * NZ;  // 33,554,432
    float* l2_out = ((long long)out_size > n_vol) ? (out + n_vol) : nullptr;

    fused_kernel<<<1024, 256>>>(x, tab, w1, b1, w2, b2, wp, bp, ws, bs,
                                out, l2_out);
}